// round 1
// baseline (speedup 1.0000x reference)
#include <cuda_runtime.h>
#include <math.h>

// Problem constants
#define B_   4
#define T_   2048
#define D_   512
#define QK_  128
#define HID_ 1024
#define NROWS (B_*T_)   // 8192
#define PROWS 4096      // padded P rows (need 0..4095)

// ---------------- scratch (static device globals; no allocation) -------------
__device__ float g_qu  [NROWS*QK_];            // q + pos_bias_u
__device__ float g_qv  [NROWS*QK_];            // q + pos_bias_v
__device__ float g_k   [NROWS*QK_];            // k
__device__ float g_v   [(size_t)NROWS*HID_];   // value
__device__ float g_gate[(size_t)NROWS*HID_];   // gate
__device__ float g_P   [(size_t)PROWS*QK_];    // reshaped position proj
__device__ float g_attn[(size_t)B_*T_*T_];     // laplace-activated scores
__device__ float g_ctx [(size_t)NROWS*HID_];   // (attn@v)*gate

__device__ __forceinline__ float siluf(float x){ return x / (1.f + __expf(-x)); }
__device__ __forceinline__ float laplacef(float x){
    // 0.5*(1+erf((x - sqrt(0.5)) / sqrt(pi/2)))
    return 0.5f*(1.f + erff((x - 0.70710678118654752f) * 0.79788456080286536f));
}

// ---------------- generic tiled SGEMM: C = A(MxK) * B(KxN), epi(z,r,c,acc) ---
#define BM 64
#define BN 64
#define BK 16

template<class Epi>
__global__ void gemm_k(const float* __restrict__ A, const float* __restrict__ Bmat,
                       int M, int N, int K, size_t strideAz, size_t strideBz, Epi epi)
{
    __shared__ float As[BM][BK+1];
    __shared__ float Bs[BK][BN+1];
    const int tid = threadIdx.x;           // 256 threads
    const int tx = tid & 15, ty = tid >> 4;
    const int bm = blockIdx.y * BM;
    const int bn = blockIdx.x * BN;
    const int z  = blockIdx.z;
    A    += (size_t)z * strideAz;
    Bmat += (size_t)z * strideBz;

    float acc[4][4] = {};
    for (int k0 = 0; k0 < K; k0 += BK) {
        #pragma unroll
        for (int e = 0; e < 4; e++) {
            int idx = tid + e*256;
            int r  = idx >> 4, c  = idx & 15;
            As[r][c] = A[(size_t)(bm+r)*K + k0 + c];
            int r2 = idx >> 6, c2 = idx & 63;
            Bs[r2][c2] = Bmat[(size_t)(k0+r2)*N + bn + c2];
        }
        __syncthreads();
        #pragma unroll
        for (int kk = 0; kk < BK; kk++) {
            float a[4], b[4];
            #pragma unroll
            for (int i=0;i<4;i++) a[i] = As[ty + 16*i][kk];
            #pragma unroll
            for (int j=0;j<4;j++) b[j] = Bs[kk][tx + 16*j];
            #pragma unroll
            for (int i=0;i<4;i++)
                #pragma unroll
                for (int j=0;j<4;j++)
                    acc[i][j] += a[i]*b[j];
        }
        __syncthreads();
    }
    #pragma unroll
    for (int i=0;i<4;i++)
        #pragma unroll
        for (int j=0;j<4;j++)
            epi(z, bm + ty + 16*i, bn + tx + 16*j, acc[i][j]);
}

// ---------------- epilogues --------------------------------------------------
struct EpiQK {  // silu + offset-scale -> qu, qv, k
    const float *b_qk, *gamma, *beta, *pbu, *pbv;
    __device__ void operator()(int, int r, int c, float acc) const {
        float t = siluf(acc + b_qk[c]);
        float q = t*gamma[c]      + beta[c];
        float k = t*gamma[QK_+c]  + beta[QK_+c];
        size_t o = (size_t)r*QK_ + c;
        g_qu[o] = q + pbu[c];
        g_qv[o] = q + pbv[c];
        g_k [o] = k;
    }
};

struct EpiHid { // silu then split into v / gate
    const float* b_hidden;
    __device__ void operator()(int, int r, int c, float acc) const {
        float t = siluf(acc + b_hidden[c]);
        if (c < HID_) g_v   [(size_t)r*HID_ + c]          = t;
        else          g_gate[(size_t)r*HID_ + (c - HID_)] = t;
    }
};

struct EpiPos { // scatter (1024,512) proj into (4096,128) reshaped layout
    __device__ void operator()(int, int r, int c, float acc) const {
        int m = r*4 + (c >> 7);
        int d = c & 127;
        g_P[(size_t)m*QK_ + d] = acc;
    }
};

struct EpiAV {  // (attn@v) * gate
    __device__ void operator()(int z, int r, int c, float acc) const {
        size_t o = ((size_t)z*T_ + r)*HID_ + c;
        g_ctx[o] = acc * g_gate[o];
    }
};

struct EpiOut { // + b_out, final output
    const float* b_out; float* out;
    __device__ void operator()(int, int r, int c, float acc) const {
        out[(size_t)r*D_ + c] = acc + b_out[c];
    }
};

// ---------------- fused scores kernel ---------------------------------------
// attn[b,i,j] = mask ? 0 : laplace( (qu[b,i].k[b,j] + qv[b,i].P[2047-i+j]) / sqrt(QK) )
__global__ void scores_kernel(const unsigned char* __restrict__ mask)
{
    __shared__ float Qus[64][33];
    __shared__ float Qvs[64][33];
    __shared__ float Ks [64][33];
    __shared__ float Ps[128][33];

    const int tid = threadIdx.x;          // 256 threads
    const int tx = tid & 15, ty = tid >> 4;
    const int b  = blockIdx.z;
    const int i0 = blockIdx.y * 64;
    const int j0 = blockIdx.x * 64;
    const int base = j0 - i0 + 1984;      // 2047 - (i0+63) + j0; in [0, 3968]

    const float* qu = g_qu + (size_t)(b*T_ + i0)*QK_;
    const float* qv = g_qv + (size_t)(b*T_ + i0)*QK_;
    const float* kp = g_k  + (size_t)(b*T_ + j0)*QK_;

    float accA[4][4] = {}, accB[4][4] = {};

    for (int kc = 0; kc < QK_; kc += 32) {
        #pragma unroll
        for (int e = 0; e < 8; e++) {      // 64x32 tiles, 8 elems/thread
            int idx = tid + e*256;
            int r = idx >> 5, c = idx & 31;
            Qus[r][c] = qu[(size_t)r*QK_ + kc + c];
            Qvs[r][c] = qv[(size_t)r*QK_ + kc + c];
            Ks [r][c] = kp[(size_t)r*QK_ + kc + c];
        }
        #pragma unroll
        for (int e = 0; e < 16; e++) {     // 128x32 band of P, 16 elems/thread
            int idx = tid + e*256;
            int r = idx >> 5, c = idx & 31;
            Ps[r][c] = g_P[(size_t)(base + r)*QK_ + kc + c];
        }
        __syncthreads();
        for (int kk = 0; kk < 32; kk++) {
            float qa[4], qb[4], kb[4];
            #pragma unroll
            for (int i=0;i<4;i++){ qa[i]=Qus[ty+16*i][kk]; qb[i]=Qvs[ty+16*i][kk]; }
            #pragma unroll
            for (int j=0;j<4;j++)  kb[j]=Ks[tx+16*j][kk];
            #pragma unroll
            for (int i=0;i<4;i++){
                int il = ty + 16*i;
                #pragma unroll
                for (int j=0;j<4;j++){
                    int jl = tx + 16*j;
                    accA[i][j] += qa[i]*kb[j];
                    accB[i][j] += qb[i]*Ps[63 - il + jl][kk];
                }
            }
        }
        __syncthreads();
    }

    const float scale = 0.088388347648318447f;   // 1/sqrt(128)
    float* attn = g_attn + ((size_t)b*T_ + i0)*T_ + j0;
    const unsigned char* mrow = mask + ((size_t)b*T_ + i0)*T_ + j0;
    #pragma unroll
    for (int i=0;i<4;i++){
        int il = ty + 16*i;
        #pragma unroll
        for (int j=0;j<4;j++){
            int jl = tx + 16*j;
            float s = (accA[i][j] + accB[i][j]) * scale;
            float a = mrow[(size_t)il*T_ + jl] ? 0.f : laplacef(s);
            attn[(size_t)il*T_ + jl] = a;
        }
    }
}

// ---------------- launch -----------------------------------------------------
extern "C" void kernel_launch(void* const* d_in, const int* in_sizes, int n_in,
                              void* d_out, int out_size)
{
    const float* qkv      = (const float*)d_in[0];
    const unsigned char* mask = (const unsigned char*)d_in[1];
    const float* pos_emb  = (const float*)d_in[2];
    const float* W_hidden = (const float*)d_in[3];
    const float* b_hidden = (const float*)d_in[4];
    const float* W_qk     = (const float*)d_in[5];
    const float* b_qk     = (const float*)d_in[6];
    const float* gamma    = (const float*)d_in[7];
    const float* beta     = (const float*)d_in[8];
    const float* W_pos    = (const float*)d_in[9];
    const float* pbu      = (const float*)d_in[10];
    const float* pbv      = (const float*)d_in[11];
    const float* W_out    = (const float*)d_in[12];
    const float* b_out    = (const float*)d_in[13];
    float* out = (float*)d_out;

    float *p_attn, *p_v, *p_ctx;
    cudaGetSymbolAddress((void**)&p_attn, g_attn);
    cudaGetSymbolAddress((void**)&p_v,    g_v);
    cudaGetSymbolAddress((void**)&p_ctx,  g_ctx);

    dim3 blk(256);

    // 1) qk projection: (8192,512)@(512,128) -> qu/qv/k
    {
        EpiQK e{b_qk, gamma, beta, pbu, pbv};
        gemm_k<EpiQK><<<dim3(QK_/BN, NROWS/BM, 1), blk>>>(qkv, W_qk, NROWS, QK_, D_, 0, 0, e);
    }
    // 2) hidden projection: (8192,512)@(512,2048) -> v, gate
    {
        EpiHid e{b_hidden};
        gemm_k<EpiHid><<<dim3(2*HID_/BN, NROWS/BM, 1), blk>>>(qkv, W_hidden, NROWS, 2*HID_, D_, 0, 0, e);
    }
    // 3) position projection (only first 1024 rows reachable): (1024,512)@(512,512)
    {
        EpiPos e{};
        gemm_k<EpiPos><<<dim3(D_/BN, 1024/BM, 1), blk>>>(pos_emb, W_pos, 1024, D_, D_, 0, 0, e);
    }
    // 4) scores + laplace (banded rel-shift fused)
    scores_kernel<<<dim3(T_/64, T_/64, B_), blk>>>(mask);

    // 5) context = (attn @ v) * gate, batched over z
    {
        EpiAV e{};
        gemm_k<EpiAV><<<dim3(HID_/BN, T_/BM, B_), blk>>>(
            p_attn, p_v, T_, HID_, T_, (size_t)T_*T_, (size_t)T_*HID_, e);
    }
    // 6) output projection: (8192,1024)@(1024,512) + b_out
    {
        EpiOut e{b_out, out};
        gemm_k<EpiOut><<<dim3(D_/BN, NROWS/BM, 1), blk>>>(p_ctx, W_out, NROWS, D_, HID_, 0, 0, e);
    }
}

// round 4
// speedup vs baseline: 1.3938x; 1.3938x over previous
#include <cuda_runtime.h>
#include <math.h>

// Problem constants
#define B_   4
#define T_   2048
#define D_   512
#define QK_  128
#define HID_ 1024
#define NROWS (B_*T_)   // 8192
#define PROWS 4096

// ---------------- scratch ----------------------------------------------------
__device__ float g_qu  [NROWS*QK_];
__device__ float g_qv  [NROWS*QK_];
__device__ float g_k   [NROWS*QK_];
__device__ float g_v   [(size_t)NROWS*HID_];
__device__ float g_gate[(size_t)NROWS*HID_];
__device__ float g_P   [(size_t)PROWS*QK_];
__device__ float g_attn[(size_t)B_*T_*T_];
__device__ float g_ctx [(size_t)NROWS*HID_];

__device__ __forceinline__ float siluf(float x){ return x / (1.f + __expf(-x)); }
__device__ __forceinline__ float laplacef(float x){
    return 0.5f*(1.f + erff((x - 0.70710678118654752f) * 0.79788456080286536f));
}

// ================= 128x128x8 double-buffered SGEMM ===========================
#define GBM 128
#define GBN 128
#define GBK 8

template<class Epi>
__global__ __launch_bounds__(256, 2)
void gemm128(const float* __restrict__ A, const float* __restrict__ Bm,
             int K, int N, size_t sAz, size_t sBz, Epi epi)
{
    __shared__ float As[2][GBK][GBM];
    __shared__ float Bs[2][GBK][GBN];
    const int tid = threadIdx.x;
    const int tx = tid & 15, ty = tid >> 4;
    const int bm = blockIdx.y * GBM;
    const int bn = blockIdx.x * GBN;
    const int z  = blockIdx.z;
    A  += (size_t)z * sAz;
    Bm += (size_t)z * sBz;

    // global load mapping
    const int arow = tid >> 1, acol = (tid & 1) * 4;   // A: 128x8, float4 along k
    const int brow = tid >> 5, bcol = (tid & 31) * 4;  // B: 8x128, float4 along n
    const float* Aptr = A  + (size_t)(bm + arow) * K + acol;
    const float* Bptr = Bm + (size_t)brow * N + bn + bcol;

    // prologue: buffer 0
    {
        float4 av = *(const float4*)Aptr;
        float4 bv = *(const float4*)Bptr;
        As[0][acol+0][arow]=av.x; As[0][acol+1][arow]=av.y;
        As[0][acol+2][arow]=av.z; As[0][acol+3][arow]=av.w;
        *(float4*)&Bs[0][brow][bcol] = bv;
    }
    __syncthreads();

    float acc[8][8] = {};
    const int nIter = K / GBK;
    int buf = 0;
    for (int it = 0; it < nIter; ++it) {
        float4 av, bv;
        const bool hasNext = (it + 1 < nIter);
        if (hasNext) {
            av = *(const float4*)(Aptr + (it+1)*GBK);
            bv = *(const float4*)(Bptr + (size_t)(it+1)*GBK*N);
        }
        #pragma unroll
        for (int kk = 0; kk < GBK; kk++) {
            float a[8], b[8];
            *(float4*)&a[0] = *(const float4*)&As[buf][kk][ty*4];
            *(float4*)&a[4] = *(const float4*)&As[buf][kk][64 + ty*4];
            *(float4*)&b[0] = *(const float4*)&Bs[buf][kk][tx*4];
            *(float4*)&b[4] = *(const float4*)&Bs[buf][kk][64 + tx*4];
            #pragma unroll
            for (int i=0;i<8;i++)
                #pragma unroll
                for (int j=0;j<8;j++)
                    acc[i][j] += a[i]*b[j];
        }
        if (hasNext) {
            int nb = buf ^ 1;
            As[nb][acol+0][arow]=av.x; As[nb][acol+1][arow]=av.y;
            As[nb][acol+2][arow]=av.z; As[nb][acol+3][arow]=av.w;
            *(float4*)&Bs[nb][brow][bcol] = bv;
            __syncthreads();
            buf = nb;
        }
    }

    #pragma unroll
    for (int i=0;i<8;i++){
        int r = bm + ((i<4) ? ty*4 + i : 64 + ty*4 + (i-4));
        #pragma unroll
        for (int j=0;j<8;j++){
            int c = bn + ((j<4) ? tx*4 + j : 64 + tx*4 + (j-4));
            epi(z, r, c, acc[i][j]);
        }
    }
}

// ---------------- epilogues --------------------------------------------------
struct EpiQK {
    const float *b_qk, *gamma, *beta, *pbu, *pbv;
    __device__ void operator()(int, int r, int c, float acc) const {
        float t = siluf(acc + b_qk[c]);
        float q = t*gamma[c]     + beta[c];
        float k = t*gamma[QK_+c] + beta[QK_+c];
        size_t o = (size_t)r*QK_ + c;
        g_qu[o] = q + pbu[c];
        g_qv[o] = q + pbv[c];
        g_k [o] = k;
    }
};
struct EpiHid {
    const float* b_hidden;
    __device__ void operator()(int, int r, int c, float acc) const {
        float t = siluf(acc + b_hidden[c]);
        if (c < HID_) g_v   [(size_t)r*HID_ + c]          = t;
        else          g_gate[(size_t)r*HID_ + (c - HID_)] = t;
    }
};
struct EpiPos {
    __device__ void operator()(int, int r, int c, float acc) const {
        int m = r*4 + (c >> 7);
        int d = c & 127;
        g_P[(size_t)m*QK_ + d] = acc;
    }
};
struct EpiAV {
    __device__ void operator()(int z, int r, int c, float acc) const {
        size_t o = ((size_t)z*T_ + r)*HID_ + c;
        g_ctx[o] = acc * g_gate[o];
    }
};
struct EpiOut {
    const float* b_out; float* out;
    __device__ void operator()(int, int r, int c, float acc) const {
        out[(size_t)r*D_ + c] = acc + b_out[c];
    }
};

// ================= fused scores kernel (128x128 tile) ========================
// attn[b,i,j] = mask ? 0 : laplace((qu[b,i].k[b,j] + qv[b,i].P[2047-i+j])/sqrt(QK))
__global__ __launch_bounds__(256, 1)
void scores128(const unsigned char* __restrict__ mask)
{
    __shared__ float Qu[2][GBK][128];
    __shared__ float Qv[2][GBK][128];
    __shared__ float Ks[2][GBK][128];
    __shared__ float Ps[2][GBK][256];

    const int tid = threadIdx.x;
    const int tx = tid & 15, ty = tid >> 4;
    const int b  = blockIdx.z;
    const int i0 = blockIdx.y * 128;
    const int j0 = blockIdx.x * 128;
    const int pbase = 1920 + j0 - i0;   // g_P row for local diag d=0 ; in [0,3840]

    const float* qu = g_qu + (size_t)(b*T_ + i0)*QK_;
    const float* qv = g_qv + (size_t)(b*T_ + i0)*QK_;
    const float* kp = g_k  + (size_t)(b*T_ + j0)*QK_;
    const float* pp = g_P  + (size_t)pbase*QK_;

    const int qrow = tid >> 1, qcol = (tid & 1) * 4;  // 128x8 tiles, 1 float4/thread

    // prologue
    {
        float4 u = *(const float4*)(qu + (size_t)qrow*QK_ + qcol);
        float4 v = *(const float4*)(qv + (size_t)qrow*QK_ + qcol);
        float4 k = *(const float4*)(kp + (size_t)qrow*QK_ + qcol);
        #pragma unroll
        for (int q=0;q<4;q++){
            Qu[0][qcol+q][qrow] = ((const float*)&u)[q];
            Qv[0][qcol+q][qrow] = ((const float*)&v)[q];
            Ks[0][qcol+q][qrow] = ((const float*)&k)[q];
        }
        #pragma unroll
        for (int s=0;s<2;s++){
            int pr = qrow + 128*s;
            float4 p = *(const float4*)(pp + (size_t)pr*QK_ + qcol);
            #pragma unroll
            for (int q=0;q<4;q++) Ps[0][qcol+q][pr] = ((const float*)&p)[q];
        }
    }
    __syncthreads();

    float acc[8][8] = {};
    const int d0 = 120 + 8*(tx - ty);   // [0,240]
    int buf = 0;
    #pragma unroll 1
    for (int it = 0; it < QK_/GBK; ++it) {
        float4 u4, v4, k4, p4a, p4b;
        const bool hasNext = (it + 1 < QK_/GBK);
        if (hasNext) {
            int kc = (it+1)*GBK + qcol;
            u4 = *(const float4*)(qu + (size_t)qrow*QK_ + kc);
            v4 = *(const float4*)(qv + (size_t)qrow*QK_ + kc);
            k4 = *(const float4*)(kp + (size_t)qrow*QK_ + kc);
            p4a = *(const float4*)(pp + (size_t)qrow*QK_ + kc);
            p4b = *(const float4*)(pp + (size_t)(qrow+128)*QK_ + kc);
        }
        #pragma unroll
        for (int kk = 0; kk < GBK; kk++) {
            float a[8], qb[8], kb[8], ps[16];
            *(float4*)&a[0]  = *(const float4*)&Qu[buf][kk][ty*8];
            *(float4*)&a[4]  = *(const float4*)&Qu[buf][kk][ty*8+4];
            *(float4*)&qb[0] = *(const float4*)&Qv[buf][kk][ty*8];
            *(float4*)&qb[4] = *(const float4*)&Qv[buf][kk][ty*8+4];
            *(float4*)&kb[0] = *(const float4*)&Ks[buf][kk][tx*8];
            *(float4*)&kb[4] = *(const float4*)&Ks[buf][kk][tx*8+4];
            *(float4*)&ps[0]  = *(const float4*)&Ps[buf][kk][d0];
            *(float4*)&ps[4]  = *(const float4*)&Ps[buf][kk][d0+4];
            *(float4*)&ps[8]  = *(const float4*)&Ps[buf][kk][d0+8];
            *(float4*)&ps[12] = *(const float4*)&Ps[buf][kk][d0+12];
            #pragma unroll
            for (int i=0;i<8;i++)
                #pragma unroll
                for (int j=0;j<8;j++)
                    acc[i][j] += a[i]*kb[j] + qb[i]*ps[7 + j - i];
        }
        if (hasNext) {
            int nb = buf ^ 1;
            #pragma unroll
            for (int q=0;q<4;q++){
                Qu[nb][qcol+q][qrow]     = ((const float*)&u4)[q];
                Qv[nb][qcol+q][qrow]     = ((const float*)&v4)[q];
                Ks[nb][qcol+q][qrow]     = ((const float*)&k4)[q];
                Ps[nb][qcol+q][qrow]     = ((const float*)&p4a)[q];
                Ps[nb][qcol+q][qrow+128] = ((const float*)&p4b)[q];
            }
            __syncthreads();
            buf = nb;
        }
    }

    const float scale = 0.088388347648318447f;   // 1/sqrt(128)
    #pragma unroll
    for (int i=0;i<8;i++){
        int il = ty*8 + i;
        const unsigned char* mrow = mask + ((size_t)(b*T_ + i0 + il))*T_ + j0;
        float* arow = g_attn + ((size_t)b*T_ + i0 + il)*T_ + j0;
        #pragma unroll
        for (int j=0;j<8;j++){
            int jl = tx*8 + j;
            float s = acc[i][j] * scale;
            arow[jl] = mrow[jl] ? 0.f : laplacef(s);
        }
    }
}

// ---------------- launch -----------------------------------------------------
extern "C" void kernel_launch(void* const* d_in, const int* in_sizes, int n_in,
                              void* d_out, int out_size)
{
    const float* qkv      = (const float*)d_in[0];
    const unsigned char* mask = (const unsigned char*)d_in[1];
    const float* pos_emb  = (const float*)d_in[2];
    const float* W_hidden = (const float*)d_in[3];
    const float* b_hidden = (const float*)d_in[4];
    const float* W_qk     = (const float*)d_in[5];
    const float* b_qk     = (const float*)d_in[6];
    const float* gamma    = (const float*)d_in[7];
    const float* beta     = (const float*)d_in[8];
    const float* W_pos    = (const float*)d_in[9];
    const float* pbu      = (const float*)d_in[10];
    const float* pbv      = (const float*)d_in[11];
    const float* W_out    = (const float*)d_in[12];
    const float* b_out    = (const float*)d_in[13];
    float* out = (float*)d_out;

    float *p_attn, *p_v, *p_ctx;
    cudaGetSymbolAddress((void**)&p_attn, g_attn);
    cudaGetSymbolAddress((void**)&p_v,    g_v);
    cudaGetSymbolAddress((void**)&p_ctx,  g_ctx);

    dim3 blk(256);

    // 1) qk projection: (8192,512)@(512,128)
    {
        EpiQK e{b_qk, gamma, beta, pbu, pbv};
        gemm128<EpiQK><<<dim3(QK_/GBN, NROWS/GBM, 1), blk>>>(qkv, W_qk, D_, QK_, 0, 0, e);
    }
    // 2) hidden projection: (8192,512)@(512,2048)
    {
        EpiHid e{b_hidden};
        gemm128<EpiHid><<<dim3(2*HID_/GBN, NROWS/GBM, 1), blk>>>(qkv, W_hidden, D_, 2*HID_, 0, 0, e);
    }
    // 3) position projection: (1024,512)@(512,512)
    {
        EpiPos e{};
        gemm128<EpiPos><<<dim3(D_/GBN, 1024/GBM, 1), blk>>>(pos_emb, W_pos, D_, D_, 0, 0, e);
    }
    // 4) scores + laplace (banded rel-shift fused)
    scores128<<<dim3(T_/128, T_/128, B_), blk>>>(mask);

    // 5) context = (attn @ v) * gate
    {
        EpiAV e{};
        gemm128<EpiAV><<<dim3(HID_/GBN, T_/GBM, B_), blk>>>(
            p_attn, p_v, T_, HID_, (size_t)T_*T_, (size_t)T_*HID_, e);
    }
    // 6) output projection: (8192,1024)@(1024,512)
    {
        EpiOut e{b_out, out};
        gemm128<EpiOut><<<dim3(D_/GBN, NROWS/GBM, 1), blk>>>(p_ctx, W_out, HID_, D_, 0, 0, e);
    }
}

// round 13
// speedup vs baseline: 1.7289x; 1.2404x over previous
#include <cuda_runtime.h>
#include <cuda_bf16.h>
#include <math.h>
#include <stdint.h>

// Problem constants
#define B_   4
#define T_   2048
#define D_   512
#define QK_  128
#define HID_ 1024
#define NROWS (B_*T_)   // 8192
#define PROWS 4096

// ---------------- scratch ----------------------------------------------------
__device__ float g_qu  [NROWS*QK_];
__device__ float g_qv  [NROWS*QK_];
__device__ float g_k   [NROWS*QK_];
__device__ float g_v   [(size_t)NROWS*HID_];
__device__ float g_gate[(size_t)NROWS*HID_];
__device__ float g_P   [(size_t)PROWS*QK_];
__device__ float g_attn[(size_t)B_*T_*T_];
__device__ float g_ctx [(size_t)NROWS*HID_];
// bf16 split operands for tensor-core attn@v
__device__ __nv_bfloat16 g_attn_h[(size_t)B_*T_*T_];
__device__ __nv_bfloat16 g_attn_l[(size_t)B_*T_*T_];
__device__ __nv_bfloat16 g_vt_h[(size_t)B_*HID_*T_];
__device__ __nv_bfloat16 g_vt_l[(size_t)B_*HID_*T_];

__device__ __forceinline__ float siluf(float x){ return x / (1.f + __expf(-x)); }
__device__ __forceinline__ float laplacef(float x){
    return 0.5f*(1.f + erff((x - 0.70710678118654752f) * 0.79788456080286536f));
}
__device__ __forceinline__ void split_bf16(float x, __nv_bfloat16& h, __nv_bfloat16& l){
    h = __float2bfloat16(x);
    l = __float2bfloat16(x - __bfloat162float(h));
}

// ---------------- mma.sync helpers (family-portable, sm_80+) ------------------
__device__ __forceinline__ uint32_t smem_u32(const void* p){
    uint32_t a;
    asm("{ .reg .u64 t; cvta.to.shared.u64 t, %1; cvt.u32.u64 %0, t; }" : "=r"(a) : "l"(p));
    return a;
}
__device__ __forceinline__ void cp16(uint32_t s, const void* g){
    asm volatile("cp.async.cg.shared.global [%0], [%1], 16;" :: "r"(s), "l"(g) : "memory");
}
__device__ __forceinline__ uint32_t lds32(uint32_t a){
    uint32_t v;
    asm volatile("ld.shared.b32 %0, [%1];" : "=r"(v) : "r"(a));
    return v;
}
__device__ __forceinline__ void mma16816(float* c, const uint32_t* a, const uint32_t* b){
    asm volatile(
        "mma.sync.aligned.m16n8k16.row.col.f32.bf16.bf16.f32 "
        "{%0,%1,%2,%3}, {%4,%5,%6,%7}, {%8,%9}, {%0,%1,%2,%3};"
        : "+f"(c[0]), "+f"(c[1]), "+f"(c[2]), "+f"(c[3])
        : "r"(a[0]), "r"(a[1]), "r"(a[2]), "r"(a[3]), "r"(b[0]), "r"(b[1]));
}

// ================= 128x128x8 double-buffered SGEMM ===========================
#define GBM 128
#define GBN 128
#define GBK 8

template<class Epi>
__global__ __launch_bounds__(256, 2)
void gemm128(const float* __restrict__ A, const float* __restrict__ Bm,
             int K, int N, size_t sAz, size_t sBz, Epi epi)
{
    __shared__ float As[2][GBK][GBM];
    __shared__ float Bs[2][GBK][GBN];
    const int tid = threadIdx.x;
    const int tx = tid & 15, ty = tid >> 4;
    const int bm = blockIdx.y * GBM;
    const int bn = blockIdx.x * GBN;
    const int z  = blockIdx.z;
    A  += (size_t)z * sAz;
    Bm += (size_t)z * sBz;

    const int arow = tid >> 1, acol = (tid & 1) * 4;
    const int brow = tid >> 5, bcol = (tid & 31) * 4;
    const float* Aptr = A  + (size_t)(bm + arow) * K + acol;
    const float* Bptr = Bm + (size_t)brow * N + bn + bcol;

    {
        float4 av = *(const float4*)Aptr;
        float4 bv = *(const float4*)Bptr;
        As[0][acol+0][arow]=av.x; As[0][acol+1][arow]=av.y;
        As[0][acol+2][arow]=av.z; As[0][acol+3][arow]=av.w;
        *(float4*)&Bs[0][brow][bcol] = bv;
    }
    __syncthreads();

    float acc[8][8] = {};
    const int nIter = K / GBK;
    int buf = 0;
    for (int it = 0; it < nIter; ++it) {
        float4 av, bv;
        const bool hasNext = (it + 1 < nIter);
        if (hasNext) {
            av = *(const float4*)(Aptr + (it+1)*GBK);
            bv = *(const float4*)(Bptr + (size_t)(it+1)*GBK*N);
        }
        #pragma unroll
        for (int kk = 0; kk < GBK; kk++) {
            float a[8], b[8];
            *(float4*)&a[0] = *(const float4*)&As[buf][kk][ty*4];
            *(float4*)&a[4] = *(const float4*)&As[buf][kk][64 + ty*4];
            *(float4*)&b[0] = *(const float4*)&Bs[buf][kk][tx*4];
            *(float4*)&b[4] = *(const float4*)&Bs[buf][kk][64 + tx*4];
            #pragma unroll
            for (int i=0;i<8;i++)
                #pragma unroll
                for (int j=0;j<8;j++)
                    acc[i][j] += a[i]*b[j];
        }
        if (hasNext) {
            int nb = buf ^ 1;
            As[nb][acol+0][arow]=av.x; As[nb][acol+1][arow]=av.y;
            As[nb][acol+2][arow]=av.z; As[nb][acol+3][arow]=av.w;
            *(float4*)&Bs[nb][brow][bcol] = bv;
            __syncthreads();
            buf = nb;
        }
    }

    #pragma unroll
    for (int i=0;i<8;i++){
        int r = bm + ((i<4) ? ty*4 + i : 64 + ty*4 + (i-4));
        #pragma unroll
        for (int j=0;j<8;j++){
            int c = bn + ((j<4) ? tx*4 + j : 64 + tx*4 + (j-4));
            epi(z, r, c, acc[i][j]);
        }
    }
}

// ---------------- epilogues --------------------------------------------------
struct EpiQK {
    const float *b_qk, *gamma, *beta, *pbu, *pbv;
    __device__ void operator()(int, int r, int c, float acc) const {
        float t = siluf(acc + b_qk[c]);
        float q = t*gamma[c]     + beta[c];
        float k = t*gamma[QK_+c] + beta[QK_+c];
        size_t o = (size_t)r*QK_ + c;
        g_qu[o] = q + pbu[c];
        g_qv[o] = q + pbv[c];
        g_k [o] = k;
    }
};
struct EpiHid {
    const float* b_hidden;
    __device__ void operator()(int, int r, int c, float acc) const {
        float t = siluf(acc + b_hidden[c]);
        if (c < HID_) g_v   [(size_t)r*HID_ + c]          = t;
        else          g_gate[(size_t)r*HID_ + (c - HID_)] = t;
    }
};
struct EpiPos {
    __device__ void operator()(int, int r, int c, float acc) const {
        int m = r*4 + (c >> 7);
        int d = c & 127;
        g_P[(size_t)m*QK_ + d] = acc;
    }
};
struct EpiOut {
    const float* b_out; float* out;
    __device__ void operator()(int, int r, int c, float acc) const {
        out[(size_t)r*D_ + c] = acc + b_out[c];
    }
};

// ================= fused scores kernel (128x128 tile) ========================
__global__ __launch_bounds__(256, 1)
void scores128(const unsigned char* __restrict__ mask)
{
    __shared__ float Qu[2][GBK][128];
    __shared__ float Qv[2][GBK][128];
    __shared__ float Ks[2][GBK][128];
    __shared__ float Ps[2][GBK][256];

    const int tid = threadIdx.x;
    const int tx = tid & 15, ty = tid >> 4;
    const int b  = blockIdx.z;
    const int i0 = blockIdx.y * 128;
    const int j0 = blockIdx.x * 128;
    const int pbase = 1920 + j0 - i0;

    const float* qu = g_qu + (size_t)(b*T_ + i0)*QK_;
    const float* qv = g_qv + (size_t)(b*T_ + i0)*QK_;
    const float* kp = g_k  + (size_t)(b*T_ + j0)*QK_;
    const float* pp = g_P  + (size_t)pbase*QK_;

    const int qrow = tid >> 1, qcol = (tid & 1) * 4;

    {
        float4 u = *(const float4*)(qu + (size_t)qrow*QK_ + qcol);
        float4 v = *(const float4*)(qv + (size_t)qrow*QK_ + qcol);
        float4 k = *(const float4*)(kp + (size_t)qrow*QK_ + qcol);
        #pragma unroll
        for (int q=0;q<4;q++){
            Qu[0][qcol+q][qrow] = ((const float*)&u)[q];
            Qv[0][qcol+q][qrow] = ((const float*)&v)[q];
            Ks[0][qcol+q][qrow] = ((const float*)&k)[q];
        }
        #pragma unroll
        for (int s=0;s<2;s++){
            int pr = qrow + 128*s;
            float4 p = *(const float4*)(pp + (size_t)pr*QK_ + qcol);
            #pragma unroll
            for (int q=0;q<4;q++) Ps[0][qcol+q][pr] = ((const float*)&p)[q];
        }
    }
    __syncthreads();

    float acc[8][8] = {};
    const int d0 = 120 + 8*(tx - ty);
    int buf = 0;
    #pragma unroll 1
    for (int it = 0; it < QK_/GBK; ++it) {
        float4 u4, v4, k4, p4a, p4b;
        const bool hasNext = (it + 1 < QK_/GBK);
        if (hasNext) {
            int kc = (it+1)*GBK + qcol;
            u4 = *(const float4*)(qu + (size_t)qrow*QK_ + kc);
            v4 = *(const float4*)(qv + (size_t)qrow*QK_ + kc);
            k4 = *(const float4*)(kp + (size_t)qrow*QK_ + kc);
            p4a = *(const float4*)(pp + (size_t)qrow*QK_ + kc);
            p4b = *(const float4*)(pp + (size_t)(qrow+128)*QK_ + kc);
        }
        #pragma unroll
        for (int kk = 0; kk < GBK; kk++) {
            float a[8], qb[8], kb[8], ps[16];
            *(float4*)&a[0]  = *(const float4*)&Qu[buf][kk][ty*8];
            *(float4*)&a[4]  = *(const float4*)&Qu[buf][kk][ty*8+4];
            *(float4*)&qb[0] = *(const float4*)&Qv[buf][kk][ty*8];
            *(float4*)&qb[4] = *(const float4*)&Qv[buf][kk][ty*8+4];
            *(float4*)&kb[0] = *(const float4*)&Ks[buf][kk][tx*8];
            *(float4*)&kb[4] = *(const float4*)&Ks[buf][kk][tx*8+4];
            *(float4*)&ps[0]  = *(const float4*)&Ps[buf][kk][d0];
            *(float4*)&ps[4]  = *(const float4*)&Ps[buf][kk][d0+4];
            *(float4*)&ps[8]  = *(const float4*)&Ps[buf][kk][d0+8];
            *(float4*)&ps[12] = *(const float4*)&Ps[buf][kk][d0+12];
            #pragma unroll
            for (int i=0;i<8;i++)
                #pragma unroll
                for (int j=0;j<8;j++)
                    acc[i][j] += a[i]*kb[j] + qb[i]*ps[7 + j - i];
        }
        if (hasNext) {
            int nb = buf ^ 1;
            #pragma unroll
            for (int q=0;q<4;q++){
                Qu[nb][qcol+q][qrow]     = ((const float*)&u4)[q];
                Qv[nb][qcol+q][qrow]     = ((const float*)&v4)[q];
                Ks[nb][qcol+q][qrow]     = ((const float*)&k4)[q];
                Ps[nb][qcol+q][qrow]     = ((const float*)&p4a)[q];
                Ps[nb][qcol+q][qrow+128] = ((const float*)&p4b)[q];
            }
            __syncthreads();
            buf = nb;
        }
    }

    const float scale = 0.088388347648318447f;
    #pragma unroll
    for (int i=0;i<8;i++){
        int il = ty*8 + i;
        const unsigned char* mrow = mask + ((size_t)(b*T_ + i0 + il))*T_ + j0;
        float* arow = g_attn + ((size_t)b*T_ + i0 + il)*T_ + j0;
        #pragma unroll
        for (int j=0;j<8;j++){
            int jl = tx*8 + j;
            float s = acc[i][j] * scale;
            arow[jl] = mrow[jl] ? 0.f : laplacef(s);
        }
    }
}

// ================= attn -> split bf16 convert ================================
__global__ __launch_bounds__(256)
void convert_attn_k()
{
    size_t i = ((size_t)blockIdx.x*blockDim.x + threadIdx.x) * 4;
    float4 a = *(const float4*)&g_attn[i];
    float v[4] = {a.x, a.y, a.z, a.w};
    __nv_bfloat16 h[4], l[4];
    #pragma unroll
    for (int q=0;q<4;q++) split_bf16(v[q], h[q], l[q]);
    __nv_bfloat162* ph = (__nv_bfloat162*)&g_attn_h[i];
    __nv_bfloat162* pl = (__nv_bfloat162*)&g_attn_l[i];
    ph[0] = __nv_bfloat162{h[0], h[1]}; ph[1] = __nv_bfloat162{h[2], h[3]};
    pl[0] = __nv_bfloat162{l[0], l[1]}; pl[1] = __nv_bfloat162{l[2], l[3]};
}

// ================= v -> v^T split bf16 transpose =============================
__global__ __launch_bounds__(256)
void transpose_v_k()
{
    __shared__ float ts[32][33];
    const int z  = blockIdx.z;
    const int t0 = blockIdx.x * 32;
    const int n0 = blockIdx.y * 32;
    const int tx = threadIdx.x, ty = threadIdx.y;  // 32 x 8

    #pragma unroll
    for (int s=0;s<32;s+=8)
        ts[ty+s][tx] = g_v[((size_t)(z*T_ + t0 + ty + s))*HID_ + n0 + tx];
    __syncthreads();
    #pragma unroll
    for (int s=0;s<32;s+=8){
        float val = ts[tx][ty+s];
        __nv_bfloat16 h, l;
        split_bf16(val, h, l);
        size_t o = ((size_t)(z*HID_ + n0 + ty + s))*T_ + t0 + tx;
        g_vt_h[o] = h;
        g_vt_l[o] = l;
    }
}

// ================= mma.sync attn@v kernel ====================================
// D[i,n] = sum_j attn[i,j]*v[j,n], split-bf16 3-term, fused *gate -> g_ctx
// CTA 256 thr (8 warps, 2x4), tile 128x128, K chunk 32 bf16, cp.async 2-stage.
#define AV_KC   32
#define AV_LDB  80                    // padded row stride in bytes (40 bf16)
#define AV_TILE (128*AV_LDB)          // 10240 B per operand tile
#define AV_BUF  (4*AV_TILE)           // Ah,Al,Bh,Bl = 40960 B
#define AV_SMEM (2*AV_BUF)            // 81920 B

__global__ __launch_bounds__(256, 1)
void av_mma_k()
{
    extern __shared__ char sm[];
    const uint32_t smb = smem_u32(sm);
    const int tid = threadIdx.x, wid = tid >> 5, lane = tid & 31;
    const int g  = lane >> 2, tq = lane & 3;
    const int wm = wid >> 2, wn = wid & 3;   // 2 (M) x 4 (N) warps
    const int z = blockIdx.z, i0 = blockIdx.y * 128, n0 = blockIdx.x * 128;

    const __nv_bfloat16* srcs[4] = {
        g_attn_h + ((size_t)(z*T_ + i0))*T_,
        g_attn_l + ((size_t)(z*T_ + i0))*T_,
        g_vt_h   + ((size_t)(z*HID_ + n0))*T_,
        g_vt_l   + ((size_t)(z*HID_ + n0))*T_ };

    const int lrow = tid >> 1, lhalf = tid & 1;   // 128 rows x 2 halves (32B each)

    // FIX (R10 NaN): each row chunk is 64 bytes (32 bf16); load TWO 16B pieces
    // per thread per operand (lhalf*32 and lhalf*32+16) = full 8192B per tile.
    auto load_chunk = [&](int c, int buf){
        const uint32_t sbase = smb + buf*AV_BUF + lrow*AV_LDB + lhalf*32;
        const size_t go = (size_t)lrow*T_ + (size_t)c*AV_KC + lhalf*16;
        #pragma unroll
        for (int t = 0; t < 4; t++){
            cp16(sbase + t*AV_TILE,      srcs[t] + go);
            cp16(sbase + t*AV_TILE + 16, srcs[t] + go + 8);
        }
        asm volatile("cp.async.commit_group;" ::: "memory");
    };

    float acc[4][4][4];
    #pragma unroll
    for (int mt=0;mt<4;mt++)
        #pragma unroll
        for (int nt=0;nt<4;nt++)
            #pragma unroll
            for (int q=0;q<4;q++) acc[mt][nt][q] = 0.f;

    load_chunk(0, 0);

    const int NCH = T_ / AV_KC;   // 64
    #pragma unroll 1
    for (int c = 0; c < NCH; c++){
        const int buf = c & 1;
        if (c + 1 < NCH){
            load_chunk(c + 1, buf ^ 1);
            asm volatile("cp.async.wait_group 1;" ::: "memory");
        } else {
            asm volatile("cp.async.wait_group 0;" ::: "memory");
        }
        __syncthreads();

        const uint32_t Ah = smb + buf*AV_BUF;
        const uint32_t Al = Ah + AV_TILE;
        const uint32_t Bh = Ah + 2*AV_TILE;
        const uint32_t Bl = Ah + 3*AV_TILE;

        #pragma unroll
        for (int kk = 0; kk < AV_KC; kk += 16){
            uint32_t ah[4][4], al[4][4], bh[4][2], bl[4][2];
            #pragma unroll
            for (int mt = 0; mt < 4; mt++){
                uint32_t b0 = (uint32_t)((wm*64 + mt*16 + g)*AV_LDB + (kk + 2*tq)*2);
                ah[mt][0] = lds32(Ah + b0);
                ah[mt][1] = lds32(Ah + b0 + 8*AV_LDB);
                ah[mt][2] = lds32(Ah + b0 + 16);
                ah[mt][3] = lds32(Ah + b0 + 8*AV_LDB + 16);
                al[mt][0] = lds32(Al + b0);
                al[mt][1] = lds32(Al + b0 + 8*AV_LDB);
                al[mt][2] = lds32(Al + b0 + 16);
                al[mt][3] = lds32(Al + b0 + 8*AV_LDB + 16);
            }
            #pragma unroll
            for (int nt = 0; nt < 4; nt++){
                uint32_t b0 = (uint32_t)((wn*32 + nt*8 + g)*AV_LDB + (kk + 2*tq)*2);
                bh[nt][0] = lds32(Bh + b0);
                bh[nt][1] = lds32(Bh + b0 + 16);
                bl[nt][0] = lds32(Bl + b0);
                bl[nt][1] = lds32(Bl + b0 + 16);
            }
            #pragma unroll
            for (int mt = 0; mt < 4; mt++)
                #pragma unroll
                for (int nt = 0; nt < 4; nt++){
                    mma16816(acc[mt][nt], ah[mt], bh[nt]);
                    mma16816(acc[mt][nt], al[mt], bh[nt]);
                    mma16816(acc[mt][nt], ah[mt], bl[nt]);
                }
        }
        __syncthreads();
    }

    // epilogue: * gate -> g_ctx (fp32)
    #pragma unroll
    for (int mt = 0; mt < 4; mt++){
        const int row0 = i0 + wm*64 + mt*16 + g;
        #pragma unroll
        for (int nt = 0; nt < 4; nt++){
            const int col = n0 + wn*32 + nt*8 + 2*tq;
            size_t o0 = ((size_t)(z*T_ + row0))*HID_ + col;
            size_t o1 = o0 + (size_t)8*HID_;
            float2 g0 = *(const float2*)&g_gate[o0];
            float2 g1 = *(const float2*)&g_gate[o1];
            float2 r0, r1;
            r0.x = acc[mt][nt][0] * g0.x;  r0.y = acc[mt][nt][1] * g0.y;
            r1.x = acc[mt][nt][2] * g1.x;  r1.y = acc[mt][nt][3] * g1.y;
            *(float2*)&g_ctx[o0] = r0;
            *(float2*)&g_ctx[o1] = r1;
        }
    }
}

// ---------------- launch -----------------------------------------------------
extern "C" void kernel_launch(void* const* d_in, const int* in_sizes, int n_in,
                              void* d_out, int out_size)
{
    const float* qkv      = (const float*)d_in[0];
    const unsigned char* mask = (const unsigned char*)d_in[1];
    const float* pos_emb  = (const float*)d_in[2];
    const float* W_hidden = (const float*)d_in[3];
    const float* b_hidden = (const float*)d_in[4];
    const float* W_qk     = (const float*)d_in[5];
    const float* b_qk     = (const float*)d_in[6];
    const float* gamma    = (const float*)d_in[7];
    const float* beta     = (const float*)d_in[8];
    const float* W_pos    = (const float*)d_in[9];
    const float* pbu      = (const float*)d_in[10];
    const float* pbv      = (const float*)d_in[11];
    const float* W_out    = (const float*)d_in[12];
    const float* b_out    = (const float*)d_in[13];
    float* out = (float*)d_out;

    float* p_ctx;
    cudaGetSymbolAddress((void**)&p_ctx, g_ctx);

    // idempotent, host-side, capture-safe; called unconditionally (no static guards)
    cudaFuncSetAttribute(av_mma_k, cudaFuncAttributeMaxDynamicSharedMemorySize, AV_SMEM);

    dim3 blk(256);

    // 1) qk projection
    {
        EpiQK e{b_qk, gamma, beta, pbu, pbv};
        gemm128<EpiQK><<<dim3(QK_/GBN, NROWS/GBM, 1), blk>>>(qkv, W_qk, D_, QK_, 0, 0, e);
    }
    // 2) hidden projection -> v, gate
    {
        EpiHid e{b_hidden};
        gemm128<EpiHid><<<dim3(2*HID_/GBN, NROWS/GBM, 1), blk>>>(qkv, W_hidden, D_, 2*HID_, 0, 0, e);
    }
    // 3) position projection
    {
        EpiPos e{};
        gemm128<EpiPos><<<dim3(D_/GBN, 1024/GBM, 1), blk>>>(pos_emb, W_pos, D_, D_, 0, 0, e);
    }
    // 3b) v -> v^T split bf16 (depends on 2)
    transpose_v_k<<<dim3(T_/32, HID_/32, B_), dim3(32,8)>>>();
    // 4) scores + laplace
    scores128<<<dim3(T_/128, T_/128, B_), blk>>>(mask);
    // 4b) attn -> split bf16
    convert_attn_k<<<(unsigned)(((size_t)B_*T_*T_/4)/256), 256>>>();
    // 5) context = (attn @ v) * gate  — mma.sync bf16 (split 3-term)
    av_mma_k<<<dim3(HID_/128, T_/128, B_), 256, AV_SMEM>>>();
    // 6) output projection
    {
        EpiOut e{b_out, out};
        gemm128<EpiOut><<<dim3(D_/GBN, NROWS/GBM, 1), blk>>>(p_ctx, W_out, HID_, D_, 0, 0, e);
    }
}

// round 17
// speedup vs baseline: 2.1536x; 1.2456x over previous
#include <cuda_runtime.h>
#include <cuda_bf16.h>
#include <math.h>
#include <stdint.h>

// Problem constants
#define B_   4
#define T_   2048
#define D_   512
#define QK_  128
#define HID_ 1024
#define NROWS (B_*T_)   // 8192
#define PROWS 4096

// ---------------- scratch ----------------------------------------------------
__device__ float g_qu  [NROWS*QK_];
__device__ float g_qv  [NROWS*QK_];
__device__ float g_k   [NROWS*QK_];
__device__ float g_v   [(size_t)NROWS*HID_];
__device__ float g_gate[(size_t)NROWS*HID_];
__device__ float g_P   [(size_t)PROWS*QK_];
__device__ float g_attn[(size_t)B_*T_*T_];
// bf16 split operands
__device__ __nv_bfloat16 g_attn_h[(size_t)B_*T_*T_];
__device__ __nv_bfloat16 g_attn_l[(size_t)B_*T_*T_];
__device__ __nv_bfloat16 g_vt_h[(size_t)B_*HID_*T_];
__device__ __nv_bfloat16 g_vt_l[(size_t)B_*HID_*T_];
__device__ __nv_bfloat16 g_qkv_h[(size_t)NROWS*D_];
__device__ __nv_bfloat16 g_qkv_l[(size_t)NROWS*D_];
__device__ __nv_bfloat16 g_ctx_h[(size_t)NROWS*HID_];
__device__ __nv_bfloat16 g_ctx_l[(size_t)NROWS*HID_];
// transposed split weights (N,K)
__device__ __nv_bfloat16 g_wqk_h [QK_*D_],      g_wqk_l [QK_*D_];
__device__ __nv_bfloat16 g_whid_h[2*HID_*D_],   g_whid_l[2*HID_*D_];
__device__ __nv_bfloat16 g_wpos_h[D_*D_],       g_wpos_l[D_*D_];
__device__ __nv_bfloat16 g_wout_h[D_*HID_],     g_wout_l[D_*HID_];

__device__ __forceinline__ float siluf(float x){ return x / (1.f + __expf(-x)); }
__device__ __forceinline__ float laplacef(float x){
    return 0.5f*(1.f + erff((x - 0.70710678118654752f) * 0.79788456080286536f));
}
__device__ __forceinline__ void split_bf16(float x, __nv_bfloat16& h, __nv_bfloat16& l){
    h = __float2bfloat16(x);
    l = __float2bfloat16(x - __bfloat162float(h));
}

// ---------------- mma.sync helpers (family-portable, sm_80+) ------------------
__device__ __forceinline__ uint32_t smem_u32(const void* p){
    uint32_t a;
    asm("{ .reg .u64 t; cvta.to.shared.u64 t, %1; cvt.u32.u64 %0, t; }" : "=r"(a) : "l"(p));
    return a;
}
__device__ __forceinline__ void cp16(uint32_t s, const void* g){
    asm volatile("cp.async.cg.shared.global [%0], [%1], 16;" :: "r"(s), "l"(g) : "memory");
}
__device__ __forceinline__ uint32_t lds32(uint32_t a){
    uint32_t v;
    asm volatile("ld.shared.b32 %0, [%1];" : "=r"(v) : "r"(a));
    return v;
}
__device__ __forceinline__ void mma16816(float* c, const uint32_t* a, const uint32_t* b){
    asm volatile(
        "mma.sync.aligned.m16n8k16.row.col.f32.bf16.bf16.f32 "
        "{%0,%1,%2,%3}, {%4,%5,%6,%7}, {%8,%9}, {%0,%1,%2,%3};"
        : "+f"(c[0]), "+f"(c[1]), "+f"(c[2]), "+f"(c[3])
        : "r"(a[0]), "r"(a[1]), "r"(a[2]), "r"(a[3]), "r"(b[0]), "r"(b[1]));
}

// tiling constants shared by all mma kernels
#define AV_KC   32
#define AV_LDB  80                    // padded row stride in bytes (40 bf16)
#define AV_TILE (128*AV_LDB)          // 10240 B per operand tile
#define AV_BUF  (4*AV_TILE)           // Ah,Al,Bh,Bl = 40960 B
#define AV_SMEM (2*AV_BUF)            // 81920 B

// ================= generic split-bf16 mma GEMM ===============================
// C[m,n] = sum_k A[m,k]*W[k,n] with A=(Ah+Al), B=(N,K) transposed weights.
template<class Epi>
__global__ __launch_bounds__(256, 1)
void gemm_mma(const __nv_bfloat16* __restrict__ Ah_, const __nv_bfloat16* __restrict__ Al_,
              const __nv_bfloat16* __restrict__ Bh_, const __nv_bfloat16* __restrict__ Bl_,
              int K, Epi epi)
{
    extern __shared__ char sm[];
    const uint32_t smb = smem_u32(sm);
    const int tid = threadIdx.x, wid = tid >> 5, lane = tid & 31;
    const int g  = lane >> 2, tq = lane & 3;
    const int wm = wid >> 2, wn = wid & 3;
    const int i0 = blockIdx.y * 128, n0 = blockIdx.x * 128;

    const __nv_bfloat16* srcs[4] = {
        Ah_ + (size_t)i0*K, Al_ + (size_t)i0*K,
        Bh_ + (size_t)n0*K, Bl_ + (size_t)n0*K };

    const int lrow = tid >> 1, lhalf = tid & 1;

    auto load_chunk = [&](int c, int buf){
        const uint32_t sbase = smb + buf*AV_BUF + lrow*AV_LDB + lhalf*32;
        const size_t go = (size_t)lrow*K + (size_t)c*AV_KC + lhalf*16;
        #pragma unroll
        for (int t = 0; t < 4; t++){
            cp16(sbase + t*AV_TILE,      srcs[t] + go);
            cp16(sbase + t*AV_TILE + 16, srcs[t] + go + 8);
        }
        asm volatile("cp.async.commit_group;" ::: "memory");
    };

    float acc[4][4][4];
    #pragma unroll
    for (int mt=0;mt<4;mt++)
        #pragma unroll
        for (int nt=0;nt<4;nt++)
            #pragma unroll
            for (int q=0;q<4;q++) acc[mt][nt][q] = 0.f;

    load_chunk(0, 0);

    const int NCH = K / AV_KC;
    #pragma unroll 1
    for (int c = 0; c < NCH; c++){
        const int buf = c & 1;
        if (c + 1 < NCH){
            load_chunk(c + 1, buf ^ 1);
            asm volatile("cp.async.wait_group 1;" ::: "memory");
        } else {
            asm volatile("cp.async.wait_group 0;" ::: "memory");
        }
        __syncthreads();

        const uint32_t Ah = smb + buf*AV_BUF;
        const uint32_t Al = Ah + AV_TILE;
        const uint32_t Bh = Ah + 2*AV_TILE;
        const uint32_t Bl = Ah + 3*AV_TILE;

        #pragma unroll
        for (int kk = 0; kk < AV_KC; kk += 16){
            uint32_t ah[4][4], al[4][4], bh[4][2], bl[4][2];
            #pragma unroll
            for (int mt = 0; mt < 4; mt++){
                uint32_t b0 = (uint32_t)((wm*64 + mt*16 + g)*AV_LDB + (kk + 2*tq)*2);
                ah[mt][0] = lds32(Ah + b0);
                ah[mt][1] = lds32(Ah + b0 + 8*AV_LDB);
                ah[mt][2] = lds32(Ah + b0 + 16);
                ah[mt][3] = lds32(Ah + b0 + 8*AV_LDB + 16);
                al[mt][0] = lds32(Al + b0);
                al[mt][1] = lds32(Al + b0 + 8*AV_LDB);
                al[mt][2] = lds32(Al + b0 + 16);
                al[mt][3] = lds32(Al + b0 + 8*AV_LDB + 16);
            }
            #pragma unroll
            for (int nt = 0; nt < 4; nt++){
                uint32_t b0 = (uint32_t)((wn*32 + nt*8 + g)*AV_LDB + (kk + 2*tq)*2);
                bh[nt][0] = lds32(Bh + b0);
                bh[nt][1] = lds32(Bh + b0 + 16);
                bl[nt][0] = lds32(Bl + b0);
                bl[nt][1] = lds32(Bl + b0 + 16);
            }
            #pragma unroll
            for (int mt = 0; mt < 4; mt++)
                #pragma unroll
                for (int nt = 0; nt < 4; nt++){
                    mma16816(acc[mt][nt], ah[mt], bh[nt]);
                    mma16816(acc[mt][nt], al[mt], bh[nt]);
                    mma16816(acc[mt][nt], ah[mt], bl[nt]);
                }
        }
        __syncthreads();
    }

    #pragma unroll
    for (int mt = 0; mt < 4; mt++){
        const int r = i0 + wm*64 + mt*16 + g;
        #pragma unroll
        for (int nt = 0; nt < 4; nt++){
            const int c = n0 + wn*32 + nt*8 + 2*tq;
            epi(r,     c,     acc[mt][nt][0]);
            epi(r,     c + 1, acc[mt][nt][1]);
            epi(r + 8, c,     acc[mt][nt][2]);
            epi(r + 8, c + 1, acc[mt][nt][3]);
        }
    }
}

// ---------------- epilogues --------------------------------------------------
struct EpiQK {
    const float *b_qk, *gamma, *beta, *pbu, *pbv;
    __device__ void operator()(int r, int c, float acc) const {
        float t = siluf(acc + b_qk[c]);
        float q = t*gamma[c]     + beta[c];
        float k = t*gamma[QK_+c] + beta[QK_+c];
        size_t o = (size_t)r*QK_ + c;
        g_qu[o] = q + pbu[c];
        g_qv[o] = q + pbv[c];
        g_k [o] = k;
    }
};
struct EpiHid {
    const float* b_hidden;
    __device__ void operator()(int r, int c, float acc) const {
        float t = siluf(acc + b_hidden[c]);
        if (c < HID_) g_v   [(size_t)r*HID_ + c]          = t;
        else          g_gate[(size_t)r*HID_ + (c - HID_)] = t;
    }
};
struct EpiPos {
    __device__ void operator()(int r, int c, float acc) const {
        int m = r*4 + (c >> 7);
        int d = c & 127;
        g_P[(size_t)m*QK_ + d] = acc;
    }
};
struct EpiOut {
    const float* b_out; float* out;
    __device__ void operator()(int r, int c, float acc) const {
        out[(size_t)r*D_ + c] = acc + b_out[c];
    }
};

// ================= fused scores kernel (128x128 tile, fp32 FMA) ==============
#define GBK 8
__global__ __launch_bounds__(256, 1)
void scores128(const unsigned char* __restrict__ mask)
{
    __shared__ float Qu[2][GBK][128];
    __shared__ float Qv[2][GBK][128];
    __shared__ float Ks[2][GBK][128];
    __shared__ float Ps[2][GBK][256];

    const int tid = threadIdx.x;
    const int tx = tid & 15, ty = tid >> 4;
    const int b  = blockIdx.z;
    const int i0 = blockIdx.y * 128;
    const int j0 = blockIdx.x * 128;
    const int pbase = 1920 + j0 - i0;

    const float* qu = g_qu + (size_t)(b*T_ + i0)*QK_;
    const float* qv = g_qv + (size_t)(b*T_ + i0)*QK_;
    const float* kp = g_k  + (size_t)(b*T_ + j0)*QK_;
    const float* pp = g_P  + (size_t)pbase*QK_;

    const int qrow = tid >> 1, qcol = (tid & 1) * 4;

    {
        float4 u = *(const float4*)(qu + (size_t)qrow*QK_ + qcol);
        float4 v = *(const float4*)(qv + (size_t)qrow*QK_ + qcol);
        float4 k = *(const float4*)(kp + (size_t)qrow*QK_ + qcol);
        #pragma unroll
        for (int q=0;q<4;q++){
            Qu[0][qcol+q][qrow] = ((const float*)&u)[q];
            Qv[0][qcol+q][qrow] = ((const float*)&v)[q];
            Ks[0][qcol+q][qrow] = ((const float*)&k)[q];
        }
        #pragma unroll
        for (int s=0;s<2;s++){
            int pr = qrow + 128*s;
            float4 p = *(const float4*)(pp + (size_t)pr*QK_ + qcol);
            #pragma unroll
            for (int q=0;q<4;q++) Ps[0][qcol+q][pr] = ((const float*)&p)[q];
        }
    }
    __syncthreads();

    float acc[8][8] = {};
    const int d0 = 120 + 8*(tx - ty);
    int buf = 0;
    #pragma unroll 1
    for (int it = 0; it < QK_/GBK; ++it) {
        float4 u4, v4, k4, p4a, p4b;
        const bool hasNext = (it + 1 < QK_/GBK);
        if (hasNext) {
            int kc = (it+1)*GBK + qcol;
            u4 = *(const float4*)(qu + (size_t)qrow*QK_ + kc);
            v4 = *(const float4*)(qv + (size_t)qrow*QK_ + kc);
            k4 = *(const float4*)(kp + (size_t)qrow*QK_ + kc);
            p4a = *(const float4*)(pp + (size_t)qrow*QK_ + kc);
            p4b = *(const float4*)(pp + (size_t)(qrow+128)*QK_ + kc);
        }
        #pragma unroll
        for (int kk = 0; kk < GBK; kk++) {
            float a[8], qb[8], kb[8], ps[16];
            *(float4*)&a[0]  = *(const float4*)&Qu[buf][kk][ty*8];
            *(float4*)&a[4]  = *(const float4*)&Qu[buf][kk][ty*8+4];
            *(float4*)&qb[0] = *(const float4*)&Qv[buf][kk][ty*8];
            *(float4*)&qb[4] = *(const float4*)&Qv[buf][kk][ty*8+4];
            *(float4*)&kb[0] = *(const float4*)&Ks[buf][kk][tx*8];
            *(float4*)&kb[4] = *(const float4*)&Ks[buf][kk][tx*8+4];
            *(float4*)&ps[0]  = *(const float4*)&Ps[buf][kk][d0];
            *(float4*)&ps[4]  = *(const float4*)&Ps[buf][kk][d0+4];
            *(float4*)&ps[8]  = *(const float4*)&Ps[buf][kk][d0+8];
            *(float4*)&ps[12] = *(const float4*)&Ps[buf][kk][d0+12];
            #pragma unroll
            for (int i=0;i<8;i++)
                #pragma unroll
                for (int j=0;j<8;j++)
                    acc[i][j] += a[i]*kb[j] + qb[i]*ps[7 + j - i];
        }
        if (hasNext) {
            int nb = buf ^ 1;
            #pragma unroll
            for (int q=0;q<4;q++){
                Qu[nb][qcol+q][qrow]     = ((const float*)&u4)[q];
                Qv[nb][qcol+q][qrow]     = ((const float*)&v4)[q];
                Ks[nb][qcol+q][qrow]     = ((const float*)&k4)[q];
                Ps[nb][qcol+q][qrow]     = ((const float*)&p4a)[q];
                Ps[nb][qcol+q][qrow+128] = ((const float*)&p4b)[q];
            }
            __syncthreads();
            buf = nb;
        }
    }

    const float scale = 0.088388347648318447f;
    #pragma unroll
    for (int i=0;i<8;i++){
        int il = ty*8 + i;
        const unsigned char* mrow = mask + ((size_t)(b*T_ + i0 + il))*T_ + j0;
        float* arow = g_attn + ((size_t)b*T_ + i0 + il)*T_ + j0;
        #pragma unroll
        for (int j=0;j<8;j++){
            int jl = tx*8 + j;
            float s = acc[i][j] * scale;
            arow[jl] = mrow[jl] ? 0.f : laplacef(s);
        }
    }
}

// ================= elementwise split converters ==============================
__global__ __launch_bounds__(256)
void convert_attn_k()
{
    size_t i = ((size_t)blockIdx.x*blockDim.x + threadIdx.x) * 4;
    float4 a = *(const float4*)&g_attn[i];
    float v[4] = {a.x, a.y, a.z, a.w};
    __nv_bfloat16 h[4], l[4];
    #pragma unroll
    for (int q=0;q<4;q++) split_bf16(v[q], h[q], l[q]);
    __nv_bfloat162* ph = (__nv_bfloat162*)&g_attn_h[i];
    __nv_bfloat162* pl = (__nv_bfloat162*)&g_attn_l[i];
    ph[0] = __nv_bfloat162{h[0], h[1]}; ph[1] = __nv_bfloat162{h[2], h[3]};
    pl[0] = __nv_bfloat162{l[0], l[1]}; pl[1] = __nv_bfloat162{l[2], l[3]};
}

__global__ __launch_bounds__(256)
void convert_qkv_k(const float* __restrict__ qkv)
{
    size_t i = ((size_t)blockIdx.x*blockDim.x + threadIdx.x) * 4;
    float4 a = *(const float4*)&qkv[i];
    float v[4] = {a.x, a.y, a.z, a.w};
    __nv_bfloat16 h[4], l[4];
    #pragma unroll
    for (int q=0;q<4;q++) split_bf16(v[q], h[q], l[q]);
    __nv_bfloat162* ph = (__nv_bfloat162*)&g_qkv_h[i];
    __nv_bfloat162* pl = (__nv_bfloat162*)&g_qkv_l[i];
    ph[0] = __nv_bfloat162{h[0], h[1]}; ph[1] = __nv_bfloat162{h[2], h[3]};
    pl[0] = __nv_bfloat162{l[0], l[1]}; pl[1] = __nv_bfloat162{l[2], l[3]};
}

// weight transpose + split: src (K,N) fp32 -> dst (N,K) bf16 h/l
__global__ __launch_bounds__(256)
void wtrans_k(const float* __restrict__ src, int K, int N,
              __nv_bfloat16* __restrict__ dh, __nv_bfloat16* __restrict__ dl)
{
    __shared__ float ts[32][33];
    const int k0 = blockIdx.x * 32;
    const int n0 = blockIdx.y * 32;
    const int tx = threadIdx.x, ty = threadIdx.y;   // 32 x 8

    #pragma unroll
    for (int s=0;s<32;s+=8)
        ts[ty+s][tx] = src[(size_t)(k0 + ty + s)*N + n0 + tx];
    __syncthreads();
    #pragma unroll
    for (int s=0;s<32;s+=8){
        float val = ts[tx][ty+s];                    // src[k0+tx][n0+ty+s]
        __nv_bfloat16 h, l;
        split_bf16(val, h, l);
        size_t o = (size_t)(n0 + ty + s)*K + k0 + tx;
        dh[o] = h;
        dl[o] = l;
    }
}

// ================= v -> v^T split bf16 transpose =============================
__global__ __launch_bounds__(256)
void transpose_v_k()
{
    __shared__ float ts[32][33];
    const int z  = blockIdx.z;
    const int t0 = blockIdx.x * 32;
    const int n0 = blockIdx.y * 32;
    const int tx = threadIdx.x, ty = threadIdx.y;  // 32 x 8

    #pragma unroll
    for (int s=0;s<32;s+=8)
        ts[ty+s][tx] = g_v[((size_t)(z*T_ + t0 + ty + s))*HID_ + n0 + tx];
    __syncthreads();
    #pragma unroll
    for (int s=0;s<32;s+=8){
        float val = ts[tx][ty+s];
        __nv_bfloat16 h, l;
        split_bf16(val, h, l);
        size_t o = ((size_t)(z*HID_ + n0 + ty + s))*T_ + t0 + tx;
        g_vt_h[o] = h;
        g_vt_l[o] = l;
    }
}

// ================= mma.sync attn@v kernel ====================================
// D[i,n] = sum_j attn[i,j]*v[j,n]; epilogue: *gate, split -> ctx_h/ctx_l
__global__ __launch_bounds__(256, 1)
void av_mma_k()
{
    extern __shared__ char sm[];
    const uint32_t smb = smem_u32(sm);
    const int tid = threadIdx.x, wid = tid >> 5, lane = tid & 31;
    const int g  = lane >> 2, tq = lane & 3;
    const int wm = wid >> 2, wn = wid & 3;
    const int z = blockIdx.z, i0 = blockIdx.y * 128, n0 = blockIdx.x * 128;

    const __nv_bfloat16* srcs[4] = {
        g_attn_h + ((size_t)(z*T_ + i0))*T_,
        g_attn_l + ((size_t)(z*T_ + i0))*T_,
        g_vt_h   + ((size_t)(z*HID_ + n0))*T_,
        g_vt_l   + ((size_t)(z*HID_ + n0))*T_ };

    const int lrow = tid >> 1, lhalf = tid & 1;

    auto load_chunk = [&](int c, int buf){
        const uint32_t sbase = smb + buf*AV_BUF + lrow*AV_LDB + lhalf*32;
        const size_t go = (size_t)lrow*T_ + (size_t)c*AV_KC + lhalf*16;
        #pragma unroll
        for (int t = 0; t < 4; t++){
            cp16(sbase + t*AV_TILE,      srcs[t] + go);
            cp16(sbase + t*AV_TILE + 16, srcs[t] + go + 8);
        }
        asm volatile("cp.async.commit_group;" ::: "memory");
    };

    float acc[4][4][4];
    #pragma unroll
    for (int mt=0;mt<4;mt++)
        #pragma unroll
        for (int nt=0;nt<4;nt++)
            #pragma unroll
            for (int q=0;q<4;q++) acc[mt][nt][q] = 0.f;

    load_chunk(0, 0);

    const int NCH = T_ / AV_KC;   // 64
    #pragma unroll 1
    for (int c = 0; c < NCH; c++){
        const int buf = c & 1;
        if (c + 1 < NCH){
            load_chunk(c + 1, buf ^ 1);
            asm volatile("cp.async.wait_group 1;" ::: "memory");
        } else {
            asm volatile("cp.async.wait_group 0;" ::: "memory");
        }
        __syncthreads();

        const uint32_t Ah = smb + buf*AV_BUF;
        const uint32_t Al = Ah + AV_TILE;
        const uint32_t Bh = Ah + 2*AV_TILE;
        const uint32_t Bl = Ah + 3*AV_TILE;

        #pragma unroll
        for (int kk = 0; kk < AV_KC; kk += 16){
            uint32_t ah[4][4], al[4][4], bh[4][2], bl[4][2];
            #pragma unroll
            for (int mt = 0; mt < 4; mt++){
                uint32_t b0 = (uint32_t)((wm*64 + mt*16 + g)*AV_LDB + (kk + 2*tq)*2);
                ah[mt][0] = lds32(Ah + b0);
                ah[mt][1] = lds32(Ah + b0 + 8*AV_LDB);
                ah[mt][2] = lds32(Ah + b0 + 16);
                ah[mt][3] = lds32(Ah + b0 + 8*AV_LDB + 16);
                al[mt][0] = lds32(Al + b0);
                al[mt][1] = lds32(Al + b0 + 8*AV_LDB);
                al[mt][2] = lds32(Al + b0 + 16);
                al[mt][3] = lds32(Al + b0 + 8*AV_LDB + 16);
            }
            #pragma unroll
            for (int nt = 0; nt < 4; nt++){
                uint32_t b0 = (uint32_t)((wn*32 + nt*8 + g)*AV_LDB + (kk + 2*tq)*2);
                bh[nt][0] = lds32(Bh + b0);
                bh[nt][1] = lds32(Bh + b0 + 16);
                bl[nt][0] = lds32(Bl + b0);
                bl[nt][1] = lds32(Bl + b0 + 16);
            }
            #pragma unroll
            for (int mt = 0; mt < 4; mt++)
                #pragma unroll
                for (int nt = 0; nt < 4; nt++){
                    mma16816(acc[mt][nt], ah[mt], bh[nt]);
                    mma16816(acc[mt][nt], al[mt], bh[nt]);
                    mma16816(acc[mt][nt], ah[mt], bl[nt]);
                }
        }
        __syncthreads();
    }

    // epilogue: *gate, split-bf16 -> ctx_h/ctx_l (feeds out-proj gemm_mma)
    #pragma unroll
    for (int mt = 0; mt < 4; mt++){
        const int row0 = i0 + wm*64 + mt*16 + g;
        #pragma unroll
        for (int nt = 0; nt < 4; nt++){
            const int col = n0 + wn*32 + nt*8 + 2*tq;
            size_t o0 = ((size_t)(z*T_ + row0))*HID_ + col;
            size_t o1 = o0 + (size_t)8*HID_;
            float2 g0 = *(const float2*)&g_gate[o0];
            float2 g1 = *(const float2*)&g_gate[o1];
            float v00 = acc[mt][nt][0]*g0.x, v01 = acc[mt][nt][1]*g0.y;
            float v10 = acc[mt][nt][2]*g1.x, v11 = acc[mt][nt][3]*g1.y;
            __nv_bfloat16 h00,l00,h01,l01,h10,l10,h11,l11;
            split_bf16(v00,h00,l00); split_bf16(v01,h01,l01);
            split_bf16(v10,h10,l10); split_bf16(v11,h11,l11);
            *(__nv_bfloat162*)&g_ctx_h[o0] = __nv_bfloat162{h00,h01};
            *(__nv_bfloat162*)&g_ctx_l[o0] = __nv_bfloat162{l00,l01};
            *(__nv_bfloat162*)&g_ctx_h[o1] = __nv_bfloat162{h10,h11};
            *(__nv_bfloat162*)&g_ctx_l[o1] = __nv_bfloat162{l10,l11};
        }
    }
}

// ---------------- launch -----------------------------------------------------
extern "C" void kernel_launch(void* const* d_in, const int* in_sizes, int n_in,
                              void* d_out, int out_size)
{
    const float* qkv      = (const float*)d_in[0];
    const unsigned char* mask = (const unsigned char*)d_in[1];
    const float* pos_emb  = (const float*)d_in[2];
    const float* W_hidden = (const float*)d_in[3];
    const float* b_hidden = (const float*)d_in[4];
    const float* W_qk     = (const float*)d_in[5];
    const float* b_qk     = (const float*)d_in[6];
    const float* gamma    = (const float*)d_in[7];
    const float* beta     = (const float*)d_in[8];
    const float* W_pos    = (const float*)d_in[9];
    const float* pbu      = (const float*)d_in[10];
    const float* pbv      = (const float*)d_in[11];
    const float* W_out    = (const float*)d_in[12];
    const float* b_out    = (const float*)d_in[13];
    float* out = (float*)d_out;

    __nv_bfloat16 *p_qkv_h, *p_qkv_l, *p_wqk_h, *p_wqk_l, *p_whid_h, *p_whid_l;
    __nv_bfloat16 *p_wpos_h, *p_wpos_l, *p_wout_h, *p_wout_l, *p_ctx_h, *p_ctx_l;
    cudaGetSymbolAddress((void**)&p_qkv_h,  g_qkv_h);
    cudaGetSymbolAddress((void**)&p_qkv_l,  g_qkv_l);
    cudaGetSymbolAddress((void**)&p_wqk_h,  g_wqk_h);
    cudaGetSymbolAddress((void**)&p_wqk_l,  g_wqk_l);
    cudaGetSymbolAddress((void**)&p_whid_h, g_whid_h);
    cudaGetSymbolAddress((void**)&p_whid_l, g_whid_l);
    cudaGetSymbolAddress((void**)&p_wpos_h, g_wpos_h);
    cudaGetSymbolAddress((void**)&p_wpos_l, g_wpos_l);
    cudaGetSymbolAddress((void**)&p_wout_h, g_wout_h);
    cudaGetSymbolAddress((void**)&p_wout_l, g_wout_l);
    cudaGetSymbolAddress((void**)&p_ctx_h,  g_ctx_h);
    cudaGetSymbolAddress((void**)&p_ctx_l,  g_ctx_l);

    // idempotent, host-side, capture-safe; called unconditionally
    cudaFuncSetAttribute(av_mma_k,          cudaFuncAttributeMaxDynamicSharedMemorySize, AV_SMEM);
    cudaFuncSetAttribute(gemm_mma<EpiQK>,   cudaFuncAttributeMaxDynamicSharedMemorySize, AV_SMEM);
    cudaFuncSetAttribute(gemm_mma<EpiHid>,  cudaFuncAttributeMaxDynamicSharedMemorySize, AV_SMEM);
    cudaFuncSetAttribute(gemm_mma<EpiPos>,  cudaFuncAttributeMaxDynamicSharedMemorySize, AV_SMEM);
    cudaFuncSetAttribute(gemm_mma<EpiOut>,  cudaFuncAttributeMaxDynamicSharedMemorySize, AV_SMEM);

    // 0) operand conversions
    convert_qkv_k<<<(unsigned)(((size_t)NROWS*D_/4)/256), 256>>>(qkv);
    wtrans_k<<<dim3(D_/32, QK_/32),    dim3(32,8)>>>(W_qk,     D_,  QK_,    p_wqk_h,  p_wqk_l);
    wtrans_k<<<dim3(D_/32, 2*HID_/32), dim3(32,8)>>>(W_hidden, D_,  2*HID_, p_whid_h, p_whid_l);
    wtrans_k<<<dim3(D_/32, D_/32),     dim3(32,8)>>>(W_pos,    D_,  D_,     p_wpos_h, p_wpos_l);
    wtrans_k<<<dim3(HID_/32, D_/32),   dim3(32,8)>>>(W_out,    HID_, D_,    p_wout_h, p_wout_l);

    // 1) qk projection (M=8192, N=128, K=512)
    {
        EpiQK e{b_qk, gamma, beta, pbu, pbv};
        gemm_mma<EpiQK><<<dim3(QK_/128, NROWS/128), 256, AV_SMEM>>>(
            p_qkv_h, p_qkv_l, p_wqk_h, p_wqk_l, D_, e);
    }
    // 2) hidden projection (M=8192, N=2048, K=512)
    {
        EpiHid e{b_hidden};
        gemm_mma<EpiHid><<<dim3(2*HID_/128, NROWS/128), 256, AV_SMEM>>>(
            p_qkv_h, p_qkv_l, p_whid_h, p_whid_l, D_, e);
    }
    // 3) position projection (M=1024, N=512, K=512).
    // convert_qkv_k(pos_emb) reuses g_qkv_h/l: safe because the in-order stream
    // guarantees the qk/hid GEMMs consumed g_qkv before this overwrite.
    {
        convert_qkv_k<<<(unsigned)(((size_t)1024*D_/4)/256), 256>>>(pos_emb);
        EpiPos e{};
        gemm_mma<EpiPos><<<dim3(D_/128, 1024/128), 256, AV_SMEM>>>(
            p_qkv_h, p_qkv_l, p_wpos_h, p_wpos_l, D_, e);
    }
    // 3b) v -> v^T split bf16
    transpose_v_k<<<dim3(T_/32, HID_/32, B_), dim3(32,8)>>>();
    // 4) scores + laplace
    scores128<<<dim3(T_/128, T_/128, B_), 256>>>(mask);
    // 4b) attn -> split bf16
    convert_attn_k<<<(unsigned)(((size_t)B_*T_*T_/4)/256), 256>>>();
    // 5) context = (attn @ v) * gate -> ctx_h/l
    av_mma_k<<<dim3(HID_/128, T_/128, B_), 256, AV_SMEM>>>();
    // 6) output projection (M=8192, N=512, K=1024)
    {
        EpiOut e{b_out, out};
        gemm_mma<EpiOut><<<dim3(D_/128, NROWS/128), 256, AV_SMEM>>>(
            p_ctx_h, p_ctx_l, p_wout_h, p_wout_l, HID_, e);
    }
}